// round 7
// baseline (speedup 1.0000x reference)
#include <cuda_runtime.h>
#include <cstdint>

// Problem constants (match reference)
#define FEAT_W   32
#define FEAT_H   32
#define HW       1024          // 32*32
#define M_GT     64
#define GT_STRIDE 14

// Output tensor offsets in floats. BN = 4096; slab = BN*HW floats.
#define SLAB     4194304ll
#define OFF_CLS   (0ll)
#define OFF_CLSW  (SLAB*1)
#define OFF_R2    (SLAB*2)
#define OFF_R2W   (SLAB*4)
#define OFF_R3    (SLAB*6)
#define OFF_R3W   (SLAB*8)
#define OFF_DL    (SLAB*10)
#define OFF_DLW   (SLAB*11)
#define OFF_DIM   (SLAB*12)
#define OFF_DIMW  (SLAB*15)
#define OFF_ROT   (SLAB*18)
#define OFF_ROTW  (SLAB*19)

__device__ __forceinline__ void stream4(float* p, float a, float b, float c, float d) {
    float4 v = make_float4(a, b, c, d);
    __stcs(reinterpret_cast<float4*>(p), v);
}

__device__ __forceinline__ uint32_t smem_u32(const void* p) {
    uint32_t a;
    asm("{ .reg .u64 t; cvta.to.shared.u64 t, %1; cvt.u32.u64 %0, t; }" : "=r"(a) : "l"(p));
    return a;
}

// Async bulk store shared->global (TMA/async path, bypasses L1 STG port)
__device__ __forceinline__ void bulk_store(float* gptr, uint32_t saddr, uint32_t bytes) {
    asm volatile("cp.async.bulk.global.shared::cta.bulk_group [%0], [%1], %2;"
                 :: "l"(gptr), "r"(saddr), "r"(bytes) : "memory");
}

__global__ __launch_bounds__(256, 8)
void rcnn3d_label_kernel(const float* __restrict__ boxes,
                         const float* __restrict__ gt_boxes,
                         const int*   __restrict__ match_pos_flag,
                         const int*   __restrict__ match_gt_id,
                         float*       __restrict__ out)
{
    const int bn  = blockIdx.x;            // b*N + n
    const int b   = bn >> 10;
    const int tid = threadIdx.x;

    __shared__ __align__(16) float sm_m2[HW];   // m2 mask map (feeds 2 dests via TMA)
    __shared__ __align__(16) float sm_m3[HW];   // m3 mask map (feeds 7 dests via TMA)
    __shared__ __align__(16) float exs[FEAT_W];
    __shared__ __align__(16) float eys[FEAT_H];

    // ---- per-box scalars (uniform; broadcast loads) ----
    const float x1 = __ldg(boxes + (size_t)bn * 4 + 0);
    const float y1 = __ldg(boxes + (size_t)bn * 4 + 1);
    const float x2 = __ldg(boxes + (size_t)bn * 4 + 2);
    const float y2 = __ldg(boxes + (size_t)bn * 4 + 3);
    const int gid  = __ldg(match_gt_id + bn);
    const int flag = __ldg(match_pos_flag + bn);

    const float* g = gt_boxes + ((size_t)b * M_GT + gid) * GT_STRIDE;
    const float kxg   = __ldg(g + 4);
    const float kyg   = __ldg(g + 5);
    const float vis   = __ldg(g + 6);
    const float dim0  = __ldg(g + 7);
    const float dim1  = __ldg(g + 8);
    const float dim2  = __ldg(g + 9);
    const float depth = __ldg(g + 12);
    const float rot   = __ldg(g + 13);

    const float cx = 0.5f * (x1 + x2);
    const float cy = 0.5f * (y1 + y2);
    const float hw = 0.5f * (x2 - x1) * 1.2f;   // EXPAND
    const float hh = 0.5f * (y2 - y1) * 1.2f;
    const float ex1 = cx - hw, ex2 = cx + hw;
    const float ey1 = cy - hh, ey2 = cy + hh;
    const float sx = (float)FEAT_W / (ex2 - ex1 + 1.0f);
    const float sy = (float)FEAT_H / (ey2 - ey1 + 1.0f);
    const float kx = (kxg - ex1) * sx;
    const float ky = (kyg - ey1) * sy;
    const bool valid = (vis != 0.0f) && (flag > 0);

    // ---- separable Gaussian tables: 64 expf per CTA ----
    if (tid < FEAT_W) {
        const float d = (float)tid + 0.5f - kx;
        exs[tid] = expf(-(d * d) / 5.12f);       // 2*SIGMA^2
    } else if (tid < FEAT_W + FEAT_H) {
        const int r = tid - FEAT_W;
        const float d = (float)r + 0.5f - ky;
        eys[r] = expf(-(d * d) / 5.12f);
    }
    __syncthreads();

    // ---- analytic 'has': peak of exs[gx]*eys[gy] at clamped-nearest cell ----
    int ixn = __float2int_rn(kx - 0.5f); ixn = min(FEAT_W - 1, max(0, ixn));
    int iyn = __float2int_rn(ky - 0.5f); iyn = min(FEAT_H - 1, max(0, iyn));
    const float smax = exs[ixn] * eys[iyn];
    const bool  has  = valid && (smax >= 0.6f);
    const float hasf = has ? 1.0f : 0.0f;

    // ---- this thread's 4 pixels: row gy, cols gx0..gx0+3 ----
    const int gy  = tid >> 3;
    const int gx0 = (tid & 7) << 2;
    const float ey   = eys[gy];
    const float offy = ky - (float)gy;
    const float4 exv = reinterpret_cast<const float4*>(exs)[tid & 7];
    const float exa[4] = {exv.x, exv.y, exv.z, exv.w};

    float sc[4], offx[4], m2f[4], m3f[4];
#pragma unroll
    for (int j = 0; j < 4; ++j) {
        const float gx = (float)(gx0 + j);
        sc[j]   = exa[j] * ey;
        offx[j] = kx - gx;
        m2f[j] = (valid && sc[j] >= 0.6f) ? 1.0f : 0.0f;
        m3f[j] = (valid && sc[j] >= 0.5f) ? 1.0f : 0.0f;   // depth thr == 3d thr
    }

    // ---- stage mask maps in SMEM, then fan out via TMA bulk stores ----
    reinterpret_cast<float4*>(sm_m2)[tid] = make_float4(m2f[0], m2f[1], m2f[2], m2f[3]);
    reinterpret_cast<float4*>(sm_m3)[tid] = make_float4(m3f[0], m3f[1], m3f[2], m3f[3]);
    __syncthreads();

    const long long pix  = (long long)tid * 4;
    const long long base = (long long)bn * HW + pix;
    const long long b2c  = (long long)bn * 2 * HW + pix;
    const long long b3c  = (long long)bn * 3 * HW + pix;

    if (tid == 0) {
        // CRITICAL: make the generic-proxy STS writes above visible to the
        // async proxy before the bulk engine reads SMEM (R6 bug: missing
        // fence -> bulk stores read stale SMEM -> 25% rel_err on reg_2d_w).
        asm volatile("fence.proxy.async.shared::cta;" ::: "memory");

        const long long mb1 = (long long)bn * HW;        // map base, C=1
        const long long mb2 = (long long)bn * 2 * HW;    // C=2
        const long long mb3 = (long long)bn * 3 * HW;    // C=3
        const uint32_t s2 = smem_u32(sm_m2);
        const uint32_t s3 = smem_u32(sm_m3);
        // m2 -> reg_2d_w (2 maps)
        bulk_store(out + OFF_R2W + mb2,          s2, 4096);
        bulk_store(out + OFF_R2W + mb2 + HW,     s2, 4096);
        // m3 -> reg_3d_w (2), depth_label_w (1), dim_label_w (3), rot_label_w (1)
        bulk_store(out + OFF_R3W + mb2,          s3, 4096);
        bulk_store(out + OFF_R3W + mb2 + HW,     s3, 4096);
        bulk_store(out + OFF_DLW + mb1,          s3, 4096);
        bulk_store(out + OFF_DIMW + mb3,         s3, 4096);
        bulk_store(out + OFF_DIMW + mb3 + HW,    s3, 4096);
        bulk_store(out + OFF_DIMW + mb3 + 2*HW,  s3, 4096);
        bulk_store(out + OFF_ROTW + mb1,         s3, 4096);
        asm volatile("cp.async.bulk.commit_group;" ::: "memory");
    }

    // ---- 11 unique maps via the regular STG path (overlaps with TMA) ----
    if (has) stream4(out + OFF_CLS + base, sc[0], sc[1], sc[2], sc[3]);
    else     stream4(out + OFF_CLS + base, -1.0f, -1.0f, -1.0f, -1.0f);
    stream4(out + OFF_CLSW + base, hasf, hasf, hasf, hasf);

    stream4(out + OFF_R2 + b2c,      offx[0]*m2f[0], offx[1]*m2f[1], offx[2]*m2f[2], offx[3]*m2f[3]);
    stream4(out + OFF_R2 + b2c + HW, offy*m2f[0],    offy*m2f[1],    offy*m2f[2],    offy*m2f[3]);

    stream4(out + OFF_R3 + b2c,      offx[0]*m3f[0], offx[1]*m3f[1], offx[2]*m3f[2], offx[3]*m3f[3]);
    stream4(out + OFF_R3 + b2c + HW, offy*m3f[0],    offy*m3f[1],    offy*m3f[2],    offy*m3f[3]);

    stream4(out + OFF_DL + base, depth*m3f[0], depth*m3f[1], depth*m3f[2], depth*m3f[3]);

    stream4(out + OFF_DIM + b3c,        dim0*m3f[0], dim0*m3f[1], dim0*m3f[2], dim0*m3f[3]);
    stream4(out + OFF_DIM + b3c + HW,   dim1*m3f[0], dim1*m3f[1], dim1*m3f[2], dim1*m3f[3]);
    stream4(out + OFF_DIM + b3c + 2*HW, dim2*m3f[0], dim2*m3f[1], dim2*m3f[2], dim2*m3f[3]);

    stream4(out + OFF_ROT + base, rot*m3f[0], rot*m3f[1], rot*m3f[2], rot*m3f[3]);

    // SMEM must stay alive until the bulk engine has read it: wait for the
    // source-read completion only (stores may still be in flight to L2).
    if (tid == 0) {
        asm volatile("cp.async.bulk.wait_group.read 0;" ::: "memory");
    }
}

extern "C" void kernel_launch(void* const* d_in, const int* in_sizes, int n_in,
                              void* d_out, int out_size) {
    const float* boxes          = (const float*)d_in[0];
    const float* gt_boxes       = (const float*)d_in[1];
    const int*   match_pos_flag = (const int*)d_in[2];
    const int*   match_gt_id    = (const int*)d_in[3];
    float* out = (float*)d_out;

    // One CTA per (b,n): duplicated mask maps go shared->global via the async
    // bulk path; the 11 unique maps go via STG.128 — two store ports in parallel.
    rcnn3d_label_kernel<<<4096, 256>>>(boxes, gt_boxes, match_pos_flag,
                                       match_gt_id, out);
}

// round 8
// speedup vs baseline: 1.0159x; 1.0159x over previous
#include <cuda_runtime.h>
#include <cstdint>

// Problem constants (match reference)
#define FEAT_W   32
#define FEAT_H   32
#define HW       1024          // 32*32
#define M_GT     64
#define GT_STRIDE 14

// Output tensor offsets in floats. BN = 4096; slab = BN*HW floats.
#define SLAB     4194304ll
#define OFF_CLS   (0ll)
#define OFF_CLSW  (SLAB*1)
#define OFF_R2    (SLAB*2)
#define OFF_R2W   (SLAB*4)
#define OFF_R3    (SLAB*6)
#define OFF_R3W   (SLAB*8)
#define OFF_DL    (SLAB*10)
#define OFF_DLW   (SLAB*11)
#define OFF_DIM   (SLAB*12)
#define OFF_DIMW  (SLAB*15)
#define OFF_ROT   (SLAB*18)
#define OFF_ROTW  (SLAB*19)

// Default write-back store (NOT .cs): dirty lines keep normal L2 priority, so
// lines still resident at the next graph replay are overwritten in L2 and
// never cost a DRAM writeback. (.cs evict-first was forfeiting those hits.)
__device__ __forceinline__ void st4(float* p, float a, float b, float c, float d) {
    float4 v = make_float4(a, b, c, d);
    *reinterpret_cast<float4*>(p) = v;
}

__global__ __launch_bounds__(256, 8)
void rcnn3d_label_kernel(const float* __restrict__ boxes,
                         const float* __restrict__ gt_boxes,
                         const int*   __restrict__ match_pos_flag,
                         const int*   __restrict__ match_gt_id,
                         float*       __restrict__ out)
{
    const int bn  = blockIdx.x;            // b*N + n
    const int b   = bn >> 10;
    const int tid = threadIdx.x;

    __shared__ __align__(16) float exs[FEAT_W];
    __shared__ __align__(16) float eys[FEAT_H];

    // ---- per-box scalars (uniform; broadcast loads) ----
    const float x1 = __ldg(boxes + (size_t)bn * 4 + 0);
    const float y1 = __ldg(boxes + (size_t)bn * 4 + 1);
    const float x2 = __ldg(boxes + (size_t)bn * 4 + 2);
    const float y2 = __ldg(boxes + (size_t)bn * 4 + 3);
    const int gid  = __ldg(match_gt_id + bn);
    const int flag = __ldg(match_pos_flag + bn);

    const float* g = gt_boxes + ((size_t)b * M_GT + gid) * GT_STRIDE;
    const float kxg   = __ldg(g + 4);
    const float kyg   = __ldg(g + 5);
    const float vis   = __ldg(g + 6);
    const float dim0  = __ldg(g + 7);
    const float dim1  = __ldg(g + 8);
    const float dim2  = __ldg(g + 9);
    const float depth = __ldg(g + 12);
    const float rot   = __ldg(g + 13);

    const float cx = 0.5f * (x1 + x2);
    const float cy = 0.5f * (y1 + y2);
    const float hw = 0.5f * (x2 - x1) * 1.2f;   // EXPAND
    const float hh = 0.5f * (y2 - y1) * 1.2f;
    const float ex1 = cx - hw, ex2 = cx + hw;
    const float ey1 = cy - hh, ey2 = cy + hh;
    const float sx = (float)FEAT_W / (ex2 - ex1 + 1.0f);
    const float sy = (float)FEAT_H / (ey2 - ey1 + 1.0f);
    const float kx = (kxg - ex1) * sx;
    const float ky = (kyg - ey1) * sy;
    const bool valid = (vis != 0.0f) && (flag > 0);

    // ---- separable Gaussian tables: 64 expf per CTA ----
    if (tid < FEAT_W) {
        const float d = (float)tid + 0.5f - kx;
        exs[tid] = expf(-(d * d) / 5.12f);       // 2*SIGMA^2
    } else if (tid < FEAT_W + FEAT_H) {
        const int r = tid - FEAT_W;
        const float d = (float)r + 0.5f - ky;
        eys[r] = expf(-(d * d) / 5.12f);
    }
    __syncthreads();

    // ---- analytic 'has': peak of exs[gx]*eys[gy] at clamped-nearest cell ----
    int ixn = __float2int_rn(kx - 0.5f); ixn = min(FEAT_W - 1, max(0, ixn));
    int iyn = __float2int_rn(ky - 0.5f); iyn = min(FEAT_H - 1, max(0, iyn));
    const float smax = exs[ixn] * eys[iyn];
    const bool  has  = valid && (smax >= 0.6f);
    const float hasf = has ? 1.0f : 0.0f;

    // ---- this thread's 4 pixels: row gy, cols gx0..gx0+3 ----
    const int gy  = tid >> 3;
    const int gx0 = (tid & 7) << 2;
    const float ey   = eys[gy];
    const float offy = ky - (float)gy;
    const float4 exv = reinterpret_cast<const float4*>(exs)[tid & 7];
    const float exa[4] = {exv.x, exv.y, exv.z, exv.w};

    float sc[4], offx[4], m2f[4], m3f[4];
#pragma unroll
    for (int j = 0; j < 4; ++j) {
        const float gx = (float)(gx0 + j);
        sc[j]   = exa[j] * ey;
        offx[j] = kx - gx;
        m2f[j] = (valid && sc[j] >= 0.6f) ? 1.0f : 0.0f;
        m3f[j] = (valid && sc[j] >= 0.5f) ? 1.0f : 0.0f;   // depth thr == 3d thr
    }

    // ---- 20 coalesced float4 stores, default .wb policy ----
    const long long pix  = (long long)tid * 4;
    const long long base = (long long)bn * HW + pix;
    const long long b2c  = (long long)bn * 2 * HW + pix;
    const long long b3c  = (long long)bn * 3 * HW + pix;

    if (has) st4(out + OFF_CLS + base, sc[0], sc[1], sc[2], sc[3]);
    else     st4(out + OFF_CLS + base, -1.0f, -1.0f, -1.0f, -1.0f);
    st4(out + OFF_CLSW + base, hasf, hasf, hasf, hasf);

    st4(out + OFF_R2  + b2c,      offx[0]*m2f[0], offx[1]*m2f[1], offx[2]*m2f[2], offx[3]*m2f[3]);
    st4(out + OFF_R2  + b2c + HW, offy*m2f[0],    offy*m2f[1],    offy*m2f[2],    offy*m2f[3]);
    st4(out + OFF_R2W + b2c,      m2f[0], m2f[1], m2f[2], m2f[3]);
    st4(out + OFF_R2W + b2c + HW, m2f[0], m2f[1], m2f[2], m2f[3]);

    st4(out + OFF_R3  + b2c,      offx[0]*m3f[0], offx[1]*m3f[1], offx[2]*m3f[2], offx[3]*m3f[3]);
    st4(out + OFF_R3  + b2c + HW, offy*m3f[0],    offy*m3f[1],    offy*m3f[2],    offy*m3f[3]);
    st4(out + OFF_R3W + b2c,      m3f[0], m3f[1], m3f[2], m3f[3]);
    st4(out + OFF_R3W + b2c + HW, m3f[0], m3f[1], m3f[2], m3f[3]);

    st4(out + OFF_DL  + base, depth*m3f[0], depth*m3f[1], depth*m3f[2], depth*m3f[3]);
    st4(out + OFF_DLW + base, m3f[0], m3f[1], m3f[2], m3f[3]);

    st4(out + OFF_DIM  + b3c,        dim0*m3f[0], dim0*m3f[1], dim0*m3f[2], dim0*m3f[3]);
    st4(out + OFF_DIM  + b3c + HW,   dim1*m3f[0], dim1*m3f[1], dim1*m3f[2], dim1*m3f[3]);
    st4(out + OFF_DIM  + b3c + 2*HW, dim2*m3f[0], dim2*m3f[1], dim2*m3f[2], dim2*m3f[3]);
    st4(out + OFF_DIMW + b3c,        m3f[0], m3f[1], m3f[2], m3f[3]);
    st4(out + OFF_DIMW + b3c + HW,   m3f[0], m3f[1], m3f[2], m3f[3]);
    st4(out + OFF_DIMW + b3c + 2*HW, m3f[0], m3f[1], m3f[2], m3f[3]);

    st4(out + OFF_ROT  + base, rot*m3f[0], rot*m3f[1], rot*m3f[2], rot*m3f[3]);
    st4(out + OFF_ROTW + base, m3f[0], m3f[1], m3f[2], m3f[3]);
}

extern "C" void kernel_launch(void* const* d_in, const int* in_sizes, int n_in,
                              void* d_out, int out_size) {
    const float* boxes          = (const float*)d_in[0];
    const float* gt_boxes       = (const float*)d_in[1];
    const int*   match_pos_flag = (const int*)d_in[2];
    const int*   match_gt_id    = (const int*)d_in[3];
    float* out = (float*)d_out;

    rcnn3d_label_kernel<<<4096, 256>>>(boxes, gt_boxes, match_pos_flag,
                                       match_gt_id, out);
}